// round 17
// baseline (speedup 1.0000x reference)
#include <cuda_runtime.h>
#include <cuda_bf16.h>
#include <cuda_fp8.h>
#include <cstdint>
#include <math.h>

#define KD 4096
#define KI 11008
#define KM 8192

#if !defined(__CUDA_ARCH__) || defined(__CUDA_ARCH_FEAT_SM103_ALL)
#define TC_OK 1
#else
#define TC_OK 0
#endif

// ---------------- persistent scratch (__device__ globals; no allocs) -------
__device__ __nv_bfloat16 g_wg[(size_t)KI * KD];   // gate w bf16 [I,D]
__device__ __nv_bfloat16 g_wu[(size_t)KI * KD];   // up   w bf16 [I,D]
__device__ __nv_bfloat16 g_wd[(size_t)KD * KI];   // down w bf16 [D,I]
__device__ unsigned char g_w8g[(size_t)KI * KD];  // e4m3(gate/64)
__device__ unsigned char g_w8u[(size_t)KI * KD];  // e4m3(up/64)
__device__ unsigned char g_w8d[(size_t)KD * KI];  // e4m3(down/2)
__device__ __nv_bfloat16 g_xh[(size_t)KM * KD];   // x hi bf16
__device__ unsigned char g_x8l[(size_t)KM * KD];  // e4m3((x-xh)*64)
__device__ __nv_bfloat16 g_hh[(size_t)KM * KI];   // h hi bf16
__device__ unsigned char g_h8l[(size_t)KM * KI];  // e4m3((h-hh)*2)
__device__ int           g_rdy[KM / 256];         // per-m-pair readiness (0..86)

// ---------------- PTX helpers ----------------------------------------------
__device__ __forceinline__ uint32_t smem_u32(const void* p) {
    return (uint32_t)__cvta_generic_to_shared(p);
}
__device__ __forceinline__ void cp16(uint32_t dst, const void* src) {
    asm volatile("cp.async.cg.shared.global [%0], [%1], 16;" :: "r"(dst), "l"(src));
}
__device__ __forceinline__ uint32_t bf16x2_of(float lo, float hi) {
    uint32_t r;
    asm("cvt.rn.bf16x2.f32 %0, %1, %2;" : "=r"(r) : "f"(hi), "f"(lo));
    return r;
}
__device__ __forceinline__ uint32_t e4m3x2_of(float lo, float hi) {
    uint16_t r;
    asm("cvt.rn.satfinite.e4m3x2.f32 %0, %1, %2;" : "=h"(r) : "f"(hi), "f"(lo));
    return (uint32_t)r;
}

#if TC_OK
__device__ __forceinline__ uint32_t ctarank() {
    uint32_t r; asm("mov.u32 %0, %%cluster_ctarank;" : "=r"(r)); return r;
}

#define CP_MBAR_ARRIVE(mb) \
    asm volatile("cp.async.mbarrier.arrive.noinc.shared::cta.b64 [%0];" :: "r"(mb) : "memory")

#define TC_ALLOC2(sa, n)  asm volatile("tcgen05.alloc.cta_group::2.sync.aligned.shared::cta.b32 [%0], %1;" :: "r"(sa), "r"(n) : "memory")
#define TC_DEALLOC2(t, n) asm volatile("tcgen05.dealloc.cta_group::2.sync.aligned.b32 %0, %1;" :: "r"(t), "r"(n))
#define TC_RELINQ2()      asm volatile("tcgen05.relinquish_alloc_permit.cta_group::2.sync.aligned;")
#define TC_COMMIT_MC2(mb, mask) asm volatile("tcgen05.commit.cta_group::2.mbarrier::arrive::one.shared::cluster.multicast::cluster.b64 [%0], %1;" :: "r"(mb), "h"((uint16_t)(mask)) : "memory")
#define TC_WAIT_LD()      asm volatile("tcgen05.wait::ld.sync.aligned;" ::: "memory")
#define TC_FENCE_AFTER()  asm volatile("tcgen05.fence::after_thread_sync;" ::: "memory")
#define TC_FENCE_BEFORE() asm volatile("tcgen05.fence::before_thread_sync;" ::: "memory")
#define FENCE_ASYNC()     asm volatile("fence.proxy.async.shared::cta;" ::: "memory")
#define MBAR_INIT(a, c)   asm volatile("mbarrier.init.shared.b64 [%0], %1;" :: "r"(a), "r"(c) : "memory")
#define CLUSTER_SYNC() do { \
    asm volatile("barrier.cluster.arrive.aligned;" ::: "memory"); \
    asm volatile("barrier.cluster.wait.aligned;"   ::: "memory"); } while (0)

__device__ __forceinline__ void mbar_arrive_cluster(uint32_t addr, uint32_t rank) {
    asm volatile("{\n\t.reg .b32 ra;\n\tmapa.shared::cluster.u32 ra, %0, %1;\n\t"
                 "mbarrier.arrive.shared::cluster.b64 _, [ra];\n\t}"
                 :: "r"(addr), "r"(rank) : "memory");
}
__device__ __forceinline__ void rdy_release(int* p) {
    asm volatile("red.release.gpu.global.add.s32 [%0], 1;" :: "l"(p) : "memory");
}
__device__ __forceinline__ int rdy_acquire(const int* p) {
    int v;
    asm volatile("ld.acquire.gpu.global.b32 %0, [%1];" : "=r"(v) : "l"(p) : "memory");
    return v;
}

#define MBAR_WAIT(mb, ph) do {                                                    \
    uint32_t _m = (mb), _p = (uint32_t)(ph), _d;                                  \
    asm volatile("{\n\t.reg .pred p;\n\t"                                         \
        "mbarrier.try_wait.parity.acquire.cta.shared::cta.b64 p, [%1], %2;\n\t"   \
        "selp.b32 %0, 1, 0, p;\n\t}" : "=r"(_d) : "r"(_m), "r"(_p) : "memory");   \
    if (!_d) {                                                                    \
        asm volatile("{\n\t.reg .pred P1;\n\tWL_%=:\n\t"                          \
            "mbarrier.try_wait.parity.acquire.cta.shared::cta.b64 P1, [%0], %1, 0x989680;\n\t" \
            "@P1 bra.uni WD_%=;\n\tbra.uni WL_%=;\n\tWD_%=:\n\t}"                 \
            :: "r"(_m), "r"(_p) : "memory");                                      \
    }                                                                             \
} while (0)

#define MBAR_WAIT_CL(mb, ph) do {                                                 \
    uint32_t _m = (mb), _p = (uint32_t)(ph), _d;                                  \
    asm volatile("{\n\t.reg .pred p;\n\t"                                         \
        "mbarrier.try_wait.parity.acquire.cluster.shared::cta.b64 p, [%1], %2;\n\t" \
        "selp.b32 %0, 1, 0, p;\n\t}" : "=r"(_d) : "r"(_m), "r"(_p) : "memory");   \
    if (!_d) {                                                                    \
        asm volatile("{\n\t.reg .pred P1;\n\tWL_%=:\n\t"                          \
            "mbarrier.try_wait.parity.acquire.cluster.shared::cta.b64 P1, [%0], %1, 0x989680;\n\t" \
            "@P1 bra.uni WD_%=;\n\tbra.uni WL_%=;\n\tWD_%=:\n\t}"                 \
            :: "r"(_m), "r"(_p) : "memory");                                      \
    }                                                                             \
} while (0)

#define LDTM32(r, ta)                                                             \
    asm volatile("tcgen05.ld.sync.aligned.32x32b.x32.b32 "                        \
        "{%0,%1,%2,%3,%4,%5,%6,%7,%8,%9,%10,%11,%12,%13,%14,%15,"                 \
        "%16,%17,%18,%19,%20,%21,%22,%23,%24,%25,%26,%27,%28,%29,%30,%31},[%32];" \
        : "=r"((r)[0]),"=r"((r)[1]),"=r"((r)[2]),"=r"((r)[3]),                    \
          "=r"((r)[4]),"=r"((r)[5]),"=r"((r)[6]),"=r"((r)[7]),                    \
          "=r"((r)[8]),"=r"((r)[9]),"=r"((r)[10]),"=r"((r)[11]),                  \
          "=r"((r)[12]),"=r"((r)[13]),"=r"((r)[14]),"=r"((r)[15]),                \
          "=r"((r)[16]),"=r"((r)[17]),"=r"((r)[18]),"=r"((r)[19]),                \
          "=r"((r)[20]),"=r"((r)[21]),"=r"((r)[22]),"=r"((r)[23]),                \
          "=r"((r)[24]),"=r"((r)[25]),"=r"((r)[26]),"=r"((r)[27]),                \
          "=r"((r)[28]),"=r"((r)[29]),"=r"((r)[30]),"=r"((r)[31])                 \
        : "r"(ta))

// SW64 (64B rows): layout 4, SBO=32 (8 rows x 64B = 512B), LBO=1
__device__ __forceinline__ uint64_t sdesc64(uint32_t addr) {
    return (4ull << 61) | (1ull << 46) | (32ull << 32) | (1ull << 16)
         | (uint64_t)((addr >> 4) & 0x3FFF);
}
// SW32 (32B rows): layout 6, SBO=16 (8 rows x 32B = 256B), LBO=1
__device__ __forceinline__ uint64_t sdesc32(uint32_t addr) {
    return (6ull << 61) | (1ull << 46) | (16ull << 32) | (1ull << 16)
         | (uint64_t)((addr >> 4) & 0x3FFF);
}
__device__ __forceinline__ uint32_t sw64o(uint32_t o) { return o ^ ((o >> 3) & 0x30); }
__device__ __forceinline__ uint32_t sw32o(uint32_t o) { return o ^ ((o >> 3) & 0x10); }

__device__ __forceinline__ void mma2(uint32_t d, uint64_t a, uint64_t b,
                                     uint32_t idesc, bool acc) {
    uint32_t en = acc ? 1u : 0u;
    asm volatile("{\n\t.reg .pred p;\n\tsetp.ne.u32 p, %5, 0;\n\t"
        "tcgen05.mma.cta_group::2.kind::f16 [%0], %1, %2, %3, "
        "{%4,%4,%4,%4,%4,%4,%4,%4}, p;\n\t}"
        :: "r"(d), "l"(a), "l"(b), "r"(idesc), "r"(0u), "r"(en) : "memory");
}
__device__ __forceinline__ void mma2_f8(uint32_t d, uint64_t a, uint64_t b,
                                        uint32_t idesc) {
    asm volatile("{\n\t.reg .pred p;\n\tsetp.ne.u32 p, 1, 0;\n\t"
        "tcgen05.mma.cta_group::2.kind::f8f6f4 [%0], %1, %2, %3, "
        "{%4,%4,%4,%4,%4,%4,%4,%4}, p;\n\t}"
        :: "r"(d), "l"(a), "l"(b), "r"(idesc), "r"(0u) : "memory");
}

#define IDESC2    ((1u << 4) | (1u << 7) | (1u << 10) | ((256u / 8) << 17) | ((256u / 16) << 24))
#define IDESC2_F8 ((1u << 4) | ((256u / 8) << 17) | ((256u / 16) << 24))
#endif // TC_OK

// ---------------- fused pre-pass (unchanged from R14/R16) --------------------
#define PREP_WB   1280
#define PREP_XB   256
#define PREP_NB   (3 * PREP_WB + PREP_XB)

__global__ void __launch_bounds__(256) prep(const int* __restrict__ gw,
                                            const int* __restrict__ uw,
                                            const int* __restrict__ dw,
                                            const float* __restrict__ x) {
    const int b = blockIdx.x;
    if (b == 0 && threadIdx.x < KM / 256) g_rdy[threadIdx.x] = 0;
    if (b < 3 * PREP_WB) {
        const int sel = b / PREP_WB;
        const int rb  = b - sel * PREP_WB;
        const int* __restrict__ w = (sel == 0) ? gw : (sel == 1) ? uw : dw;
        __nv_bfloat16* o  = (sel == 0) ? g_wg : (sel == 1) ? g_wu : g_wd;
        unsigned char* o8 = (sel == 0) ? g_w8g : (sel == 1) ? g_w8u : g_w8d;
        const float sc8 = (sel == 2) ? 0.5f : (1.0f / 64.0f);
        const long n4 = (long)KI * KD / 4;
        const long step = (long)PREP_WB * 256;
        for (long j = (long)rb * 256 + threadIdx.x; j < n4; j += step) {
            const int4 v = __ldcs(&((const int4*)w)[j]);
            const float f0 = (float)v.x, f1 = (float)v.y;
            const float f2 = (float)v.z, f3 = (float)v.w;
            uint2 pb;
            pb.x = bf16x2_of(f0, f1);
            pb.y = bf16x2_of(f2, f3);
            __stcs(&((uint2*)o)[j], pb);
            const uint32_t q = e4m3x2_of(f0 * sc8, f1 * sc8)
                             | (e4m3x2_of(f2 * sc8, f3 * sc8) << 16);
            __stcs(&((uint32_t*)o8)[j], q);
        }
    } else {
        const int rb = b - 3 * PREP_WB;
        const long x4 = (long)KM * KD / 4;
        const long step = (long)PREP_XB * 256;
        for (long i = (long)rb * 256 + threadIdx.x; i < x4; i += step) {
            const float4 v = __ldcs(&((const float4*)x)[i]);
            const uint32_t h01 = bf16x2_of(v.x, v.y);
            const uint32_t h23 = bf16x2_of(v.z, v.w);
            const float a0 = __uint_as_float(h01 << 16);
            const float a1 = __uint_as_float(h01 & 0xFFFF0000u);
            const float a2 = __uint_as_float(h23 << 16);
            const float a3 = __uint_as_float(h23 & 0xFFFF0000u);
            uint2 ph; ph.x = h01; ph.y = h23;
            __stcs(&((uint2*)g_xh)[i], ph);
            const uint32_t l = e4m3x2_of((v.x - a0) * 64.0f, (v.y - a1) * 64.0f)
                             | (e4m3x2_of((v.z - a2) * 64.0f, (v.w - a3) * 64.0f) << 16);
            __stcs(&((uint32_t*)g_x8l)[i], l);
        }
    }
}

// ---------------- fused persistent GEMM: 6-stage K=32 pipeline ---------------
#define NPAIR    74
#define NTHR     288
#define NSTG     6
#define SST      36864                   // AH8K B0 8K B1 8K AL4K B0L4K B1L4K
#define OF_AH    0
#define OF_B0    8192
#define OF_B1    16384
#define OF_AL    24576
#define OF_B0L   28672
#define OF_B1L   32768
#define GSMEM    (NSTG * SST + 1024)     // 222208

#define K1_NC    (KD / 32)               // 128 chunks / k1 tile
#define K1_NT    (KI / 256)              // 43
#define K1_GM    16
#define K1_TILES (K1_NT * (KM / 256))    // 1376
#define K2_NC    (KI / 32)               // 344 chunks / k2 tile
#define K2_NT    (KD / 512)              // 8
#define K2_GM    8
#define K2_TILES (K2_NT * (KM / 256))    // 256
#define RDY_TGT  (2 * K1_NT)             // 86

// jointly balanced schedule (R16, validated)
__device__ __forceinline__ int k1_tile(int pair, int r) {
    if (r < 17) return r * NPAIR + pair;
    if (pair < 34) return -1;
    if (r == 17) return 17 * NPAIR + (pair - 34);
    if (r == 18) return 17 * NPAIR + 40 + (pair - 34);
    return (pair < 72) ? 17 * NPAIR + 80 + (pair - 34) : -1;
}
__device__ __forceinline__ int k2_tile(int pair, int r) {
    if (r < 3) return r * NPAIR + pair;
    return (pair < 34) ? 3 * NPAIR + pair : -1;
}
#define K1_ROUNDS 20
#define K2_ROUNDS 4

extern __shared__ char dsm[];

#if TC_OK
__global__ void __launch_bounds__(NTHR, 1) __cluster_dims__(2, 1, 1)
kmain(const float* __restrict__ gs_p, const float* __restrict__ us_p,
      const float* __restrict__ ds_p, float* __restrict__ out)
{
    const int t = threadIdx.x, wid = t >> 5, lane = t & 31;
    const uint32_t rank = ctarank();
    const int pair = blockIdx.y;
    const uint32_t sb = (smem_u32(dsm) + 1023u) & ~1023u;

    __shared__ uint32_t s_tm[1];
    __shared__ alignas(8) uint64_t s_mb[20];  // full[6], rdy[6], done[6], tdone, epi

    if (wid == 8) TC_ALLOC2(smem_u32(s_tm), 512);
    if (t == 0) {
#pragma unroll
        for (int i = 0; i < NSTG; ++i) {
            MBAR_INIT(smem_u32(&s_mb[i]),           128);  // full
            MBAR_INIT(smem_u32(&s_mb[NSTG + i]),    2);    // rdy
            MBAR_INIT(smem_u32(&s_mb[2 * NSTG + i]), 1);   // done
        }
        MBAR_INIT(smem_u32(&s_mb[18]), 1);                 // tdone
        MBAR_INIT(smem_u32(&s_mb[19]), 2);                 // epi
    }
    __syncthreads();
    CLUSTER_SYNC();
    uint32_t tm;
    asm volatile("ld.shared.b32 %0, [%1];" : "=r"(tm) : "r"(smem_u32(s_tm)));
    const uint32_t full0 = smem_u32(&s_mb[0]), rdy0 = smem_u32(&s_mb[NSTG]);
    const uint32_t done0 = smem_u32(&s_mb[2 * NSTG]);
    const uint32_t tdone = smem_u32(&s_mb[18]), epib = smem_u32(&s_mb[19]);

    if (t >= 128 && t < 256) {
        // =============== producers ===============
        const int tp  = t - 128;
        const int cb  = tp & 3;                     // bf16: 4 x 16B cols
        const int rb  = tp >> 2;                    // 0..31
        const int c2  = tp & 1;                     // fp8: 2 x 16B cols
        const int r2  = tp >> 1;                    // 0..63
        long q = 0;
        for (int rr = 0; rr < K1_ROUNDS; ++rr) {                  // ---- k1 ----
            const int idx = k1_tile(pair, rr);
            if (idx < 0) continue;
            const int band = idx / (K1_NT * K1_GM);
            const int rsub = idx % (K1_NT * K1_GM);
            const int n0   = (rsub / K1_GM) * 256;
            const int mp   = band * K1_GM + rsub % K1_GM;
            const int m0   = (mp * 2 + (int)rank) * 128;
            const __nv_bfloat16* pxh = g_xh + (size_t)(m0 + rb) * KD + cb * 8;
            const __nv_bfloat16* pg  = g_wg + (size_t)(n0 + rank * 128 + rb) * KD + cb * 8;
            const __nv_bfloat16* pu  = g_wu + (size_t)(n0 + rank * 128 + rb) * KD + cb * 8;
            const unsigned char* pxl = g_x8l + (size_t)(m0 + r2) * KD + c2 * 16;
            const unsigned char* pg8 = g_w8g + (size_t)(n0 + rank * 128 + r2) * KD + c2 * 16;
            const unsigned char* pu8 = g_w8u + (size_t)(n0 + rank * 128 + r2) * KD + c2 * 16;
            for (int c = 0; c < K1_NC; ++c, ++q) {
                const int s = (int)(q % NSTG);
                if (q >= NSTG) MBAR_WAIT(done0 + s * 8, (int)((q / NSTG - 1) & 1));
                const int k0 = c * 32;
                const uint32_t st = sb + s * SST;
#pragma unroll
                for (int i = 0; i < 4; ++i) {
                    const uint32_t d = sw64o((uint32_t)((rb + 32 * i) * 64 + cb * 16));
                    const size_t go = (size_t)(32 * i) * KD + k0;
                    cp16(st + OF_AH + d, pxh + go);
                    cp16(st + OF_B0 + d, pg + go);
                    cp16(st + OF_B1 + d, pu + go);
                }
#pragma unroll
                for (int i = 0; i < 2; ++i) {
                    const uint32_t d = sw32o((uint32_t)((r2 + 64 * i) * 32 + c2 * 16));
                    const size_t go = (size_t)(64 * i) * KD + k0;
                    cp16(st + OF_AL  + d, pxl + go);
                    cp16(st + OF_B0L + d, pg8 + go);
                    cp16(st + OF_B1L + d, pu8 + go);
                }
                CP_MBAR_ARRIVE(full0 + s * 8);
            }
        }
        for (int rr = 0; rr < K2_ROUNDS; ++rr) {                  // ---- k2 ----
            const int idx = k2_tile(pair, rr);
            if (idx < 0) continue;
            const int band = idx / (K2_NT * K2_GM);
            const int rsub = idx % (K2_NT * K2_GM);
            const int n0   = (rsub / K2_GM) * 512;
            const int mp   = band * K2_GM + rsub % K2_GM;
            const int m0   = (mp * 2 + (int)rank) * 128;
            while (rdy_acquire(&g_rdy[mp]) < RDY_TGT) __nanosleep(128);
            const __nv_bfloat16* pah = g_hh + (size_t)(m0 + rb) * KI + cb * 8;
            const __nv_bfloat16* pb0 = g_wd + (size_t)(n0 +       rank * 128 + rb) * KI + cb * 8;
            const __nv_bfloat16* pb1 = g_wd + (size_t)(n0 + 256 + rank * 128 + rb) * KI + cb * 8;
            const unsigned char* pal = g_h8l + (size_t)(m0 + r2) * KI + c2 * 16;
            const unsigned char* p08 = g_w8d + (size_t)(n0 +       rank * 128 + r2) * KI + c2 * 16;
            const unsigned char* p18 = g_w8d + (size_t)(n0 + 256 + rank * 128 + r2) * KI + c2 * 16;
            for (int c = 0; c < K2_NC; ++c, ++q) {
                const int s = (int)(q % NSTG);
                if (q >= NSTG) MBAR_WAIT(done0 + s * 8, (int)((q / NSTG - 1) & 1));
                const int k0 = c * 32;
                const uint32_t st = sb + s * SST;
#pragma unroll
                for (int i = 0; i < 4; ++i) {
                    const uint32_t d = sw64o((uint32_t)((rb + 32 * i) * 64 + cb * 16));
                    const size_t go = (size_t)(32 * i) * KI + k0;
                    cp16(st + OF_AH + d, pah + go);
                    cp16(st + OF_B0 + d, pb0 + go);
                    cp16(st + OF_B1 + d, pb1 + go);
                }
#pragma unroll
                for (int i = 0; i < 2; ++i) {
                    const uint32_t d = sw32o((uint32_t)((r2 + 64 * i) * 32 + c2 * 16));
                    const size_t go = (size_t)(64 * i) * KI + k0;
                    cp16(st + OF_AL  + d, pal + go);
                    cp16(st + OF_B0L + d, p08 + go);
                    cp16(st + OF_B1L + d, p18 + go);
                }
                CP_MBAR_ARRIVE(full0 + s * 8);
            }
        }
    } else if (t == 257) {
        // =============== relay ===============
        long q = 0;
        for (int rr = 0; rr < K1_ROUNDS; ++rr) {
            if (k1_tile(pair, rr) < 0) continue;
            for (int c = 0; c < K1_NC; ++c, ++q) {
                const int s = (int)(q % NSTG);
                MBAR_WAIT(full0 + s * 8, (int)((q / NSTG) & 1));
                FENCE_ASYNC();
                mbar_arrive_cluster(rdy0 + s * 8, 0);
            }
        }
        for (int rr = 0; rr < K2_ROUNDS; ++rr) {
            if (k2_tile(pair, rr) < 0) continue;
            for (int c = 0; c < K2_NC; ++c, ++q) {
                const int s = (int)(q % NSTG);
                MBAR_WAIT(full0 + s * 8, (int)((q / NSTG) & 1));
                FENCE_ASYNC();
                mbar_arrive_cluster(rdy0 + s * 8, 0);
            }
        }
    } else if (rank == 0 && t == 256) {
        // =============== MMA leader ===============
        long q = 0; int it = 0;
        for (int rr = 0; rr < K1_ROUNDS; ++rr) {
            if (k1_tile(pair, rr) < 0) continue;
            if (it > 0) MBAR_WAIT_CL(epib, (it - 1) & 1);
            for (int c = 0; c < K1_NC; ++c, ++q) {
                const int s = (int)(q % NSTG);
                MBAR_WAIT_CL(rdy0 + s * 8, (int)((q / NSTG) & 1));
                const uint32_t st = sb + s * SST;
                const uint64_t da = sdesc64(st + OF_AH);
                const uint64_t dg = sdesc64(st + OF_B0), du = sdesc64(st + OF_B1);
                const uint64_t dal = sdesc32(st + OF_AL);
                const uint64_t dgl = sdesc32(st + OF_B0L), dul = sdesc32(st + OF_B1L);
#pragma unroll
                for (int k = 0; k < 2; ++k) {          // bf16: K=16/dispatch
                    const bool acc = (c > 0) || (k > 0);
                    mma2(tm,       da + 2 * k, dg + 2 * k, IDESC2, acc);
                    mma2(tm + 256, da + 2 * k, du + 2 * k, IDESC2, acc);
                }
                mma2_f8(tm,       dal, dgl, IDESC2_F8);   // fp8: K=32/dispatch
                mma2_f8(tm + 256, dal, dul, IDESC2_F8);
                TC_COMMIT_MC2(done0 + s * 8, 0x3);
                if (c == K1_NC - 1) TC_COMMIT_MC2(tdone, 0x3);
            }
            ++it;
        }
        for (int rr = 0; rr < K2_ROUNDS; ++rr) {
            if (k2_tile(pair, rr) < 0) continue;
            MBAR_WAIT_CL(epib, (it - 1) & 1);
            for (int c = 0; c < K2_NC; ++c, ++q) {
                const int s = (int)(q % NSTG);
                MBAR_WAIT_CL(rdy0 + s * 8, (int)((q / NSTG) & 1));
                const uint32_t st = sb + s * SST;
                const uint64_t da = sdesc64(st + OF_AH);
                const uint64_t d0 = sdesc64(st + OF_B0), d1 = sdesc64(st + OF_B1);
                const uint64_t dal = sdesc32(st + OF_AL);
                const uint64_t d0l = sdesc32(st + OF_B0L), d1l = sdesc32(st + OF_B1L);
#pragma unroll
                for (int k = 0; k < 2; ++k) {
                    const bool acc = (c > 0) || (k > 0);
                    mma2(tm,       da + 2 * k, d0 + 2 * k, IDESC2, acc);
                    mma2(tm + 256, da + 2 * k, d1 + 2 * k, IDESC2, acc);
                }
                mma2_f8(tm,       dal, d0l, IDESC2_F8);
                mma2_f8(tm + 256, dal, d1l, IDESC2_F8);
                TC_COMMIT_MC2(done0 + s * 8, 0x3);
                if (c == K2_NC - 1) TC_COMMIT_MC2(tdone, 0x3);
            }
            ++it;
        }
    } else if (t < 128) {
        // =============== consumers ===============
        const float gsc = gs_p[0], usc = us_p[0], dsc = ds_p[0];
        int it = 0;
        for (int rr = 0; rr < K1_ROUNDS; ++rr) {                  // ---- k1 ----
            const int idx = k1_tile(pair, rr);
            if (idx < 0) continue;
            const int band = idx / (K1_NT * K1_GM);
            const int rsub = idx % (K1_NT * K1_GM);
            const int n0   = (rsub / K1_GM) * 256;
            const int mp   = band * K1_GM + rsub % K1_GM;
            const int m0   = (mp * 2 + (int)rank) * 128;
            MBAR_WAIT(tdone, it & 1);
            TC_FENCE_AFTER();
            const int m = m0 + wid * 32 + lane;
#pragma unroll 1
            for (int cb2 = 0; cb2 < 8; ++cb2) {
                uint32_t rg[32], ru[32];
                LDTM32(rg, tm + cb2 * 32);
                LDTM32(ru, tm + 256 + cb2 * 32);
                TC_WAIT_LD();
                alignas(16) ushort oh[32];
                alignas(16) unsigned char ol8[32];
#pragma unroll
                for (int j = 0; j < 32; ++j) {
                    const float g = __uint_as_float(rg[j]) * gsc;
                    const float u = __uint_as_float(ru[j]) * usc;
                    const float v = (g / (1.0f + __expf(-g))) * u;
                    const __nv_bfloat16 hh = __float2bfloat16(v);
                    oh[j] = *(const ushort*)&hh;
                    ol8[j] = __nv_fp8_e4m3((v - __bfloat162float(hh)) * 2.0f).__x;
                }
                const size_t eoff = (size_t)m * KI + n0 + cb2 * 32;
#pragma unroll
                for (int qq = 0; qq < 4; ++qq)
                    *(uint4*)((char*)g_hh + eoff * 2 + qq * 16) = *(uint4*)&oh[qq * 8];
#pragma unroll
                for (int qq = 0; qq < 2; ++qq)
                    *(uint4*)(g_h8l + eoff + qq * 16) = *(uint4*)&ol8[qq * 16];
            }
            TC_FENCE_BEFORE();
            asm volatile("bar.sync 1, 128;" ::: "memory");
            if (t == 0) {
                mbar_arrive_cluster(epib, 0);
                rdy_release(&g_rdy[mp]);
            }
            ++it;
        }
        for (int rr = 0; rr < K2_ROUNDS; ++rr) {                  // ---- k2 ----
            const int idx = k2_tile(pair, rr);
            if (idx < 0) continue;
            const int band = idx / (K2_NT * K2_GM);
            const int rsub = idx % (K2_NT * K2_GM);
            const int n0   = (rsub / K2_GM) * 512;
            const int mp   = band * K2_GM + rsub % K2_GM;
            const int m0   = (mp * 2 + (int)rank) * 128;
            MBAR_WAIT(tdone, it & 1);
            TC_FENCE_AFTER();
            const int m = m0 + wid * 32 + lane;
#pragma unroll 1
            for (int cb2 = 0; cb2 < 16; ++cb2) {
                uint32_t r[32];
                LDTM32(r, tm + cb2 * 32);
                TC_WAIT_LD();
                float* p = out + (size_t)m * KD + n0 + cb2 * 32;
#pragma unroll
                for (int qq = 0; qq < 8; ++qq) {
                    float4 v;
                    v.x = __uint_as_float(r[qq * 4 + 0]) * dsc;
                    v.y = __uint_as_float(r[qq * 4 + 1]) * dsc;
                    v.z = __uint_as_float(r[qq * 4 + 2]) * dsc;
                    v.w = __uint_as_float(r[qq * 4 + 3]) * dsc;
                    *(float4*)(p + qq * 4) = v;
                }
            }
            TC_FENCE_BEFORE();
            asm volatile("bar.sync 1, 128;" ::: "memory");
            if (t == 0) mbar_arrive_cluster(epib, 0);
            ++it;
        }
    }
    __syncthreads();
    if (wid == 8) { TC_RELINQ2(); TC_DEALLOC2(tm, 512); }
    CLUSTER_SYNC();
}

#else  // ---------------- SIMT fallback kmain (compile-only) -------------------
__global__ void __launch_bounds__(NTHR, 1)
kmain(const float* __restrict__ gs_p, const float* __restrict__ us_p,
      const float* __restrict__ ds_p, float* __restrict__ out)
{
    const int t = threadIdx.x;
    const float gsc = gs_p[0], usc = us_p[0], dsc = ds_p[0];
    for (int rr = 0; rr < K1_ROUNDS; ++rr) {
        const int idx = k1_tile(blockIdx.y, rr);
        if (idx < 0) continue;
        const int band = idx / (K1_NT * K1_GM);
        const int rsub = idx % (K1_NT * K1_GM);
        const int n0   = (rsub / K1_GM) * 256;
        const int mp   = band * K1_GM + rsub % K1_GM;
        const int m0   = (mp * 2 + blockIdx.x) * 128;
        for (int e = t; e < 128 * 256; e += blockDim.x) {
            const int r = e >> 8, col = e & 255;
            const int m = m0 + r;
            float ag = 0.f, au = 0.f;
            for (int k = 0; k < KD; ++k) {
                const float xv = __bfloat162float(g_xh[(size_t)m * KD + k]);
                ag += xv * __bfloat162float(g_wg[(size_t)(n0 + col) * KD + k]);
                au += xv * __bfloat162float(g_wu[(size_t)(n0 + col) * KD + k]);
            }
            const float g = ag * gsc;
            const float v = (g / (1.0f + __expf(-g))) * (au * usc);
            const __nv_bfloat16 hh = __float2bfloat16(v);
            g_hh[(size_t)m * KI + n0 + col] = hh;
            g_h8l[(size_t)m * KI + n0 + col] =
                __nv_fp8_e4m3((v - __bfloat162float(hh)) * 2.0f).__x;
        }
        __syncthreads();
        if (t == 0) atomicAdd(&g_rdy[mp], 2);
    }
    for (int rr = 0; rr < K2_ROUNDS; ++rr) {
        const int idx = k2_tile(blockIdx.y, rr);
        if (idx < 0) continue;
        const int band = idx / (K2_NT * K2_GM);
        const int rsub = idx % (K2_NT * K2_GM);
        const int n0   = (rsub / K2_GM) * 512;
        const int mp   = band * K2_GM + rsub % K2_GM;
        const int m0   = (mp * 2 + blockIdx.x) * 128;
        if (t == 0) while (atomicAdd(&g_rdy[mp], 0) < RDY_TGT) {}
        __syncthreads();
        for (int e = t; e < 128 * 512; e += blockDim.x) {
            const int r = e >> 9, col = e & 511;
            const int m = m0 + r;
            float acc = 0.f;
            for (int k = 0; k < KI; ++k)
                acc += __bfloat162float(g_hh[(size_t)m * KI + k])
                     * __bfloat162float(g_wd[(size_t)(n0 + col) * KI + k]);
            out[(size_t)m * KD + n0 + col] = acc * dsc;
        }
    }
}
#endif

// ---------------- launch ------------------------------------------------------
extern "C" void kernel_launch(void* const* d_in, const int* in_sizes, int n_in,
                              void* d_out, int out_size)
{
    const float* x  = (const float*)d_in[0];
    const int*   gw = (const int*)  d_in[1];
    const float* gs = (const float*)d_in[2];
    const int*   uw = (const int*)  d_in[3];
    const float* us = (const float*)d_in[4];
    const int*   dw = (const int*)  d_in[5];
    const float* ds = (const float*)d_in[6];
    float* out = (float*)d_out;

    cudaFuncSetAttribute(kmain, cudaFuncAttributeMaxDynamicSharedMemorySize, GSMEM);

    prep<<<PREP_NB, 256>>>(gw, uw, dw, x);
    kmain<<<dim3(2, NPAIR, 1), NTHR, GSMEM>>>(gs, us, ds, out);
}